// round 1
// baseline (speedup 1.0000x reference)
#include <cuda_runtime.h>

#define THREADS 256
#define ROWS    256     // rows per block (1 per thread)
#define KC      64      // k-chunk staged in shared
#define XPAD    66      // words per staged row (even -> 8B align, tid*33 mod 32 distinct)

typedef unsigned long long u64;

__device__ __forceinline__ void rodrigues(float v0, float v1, float v2, float* R) {
    float th = sqrtf(v0 * v0 + v1 * v1 + v2 * v2);
    float ux = v0 / th, uy = v1 / th, uz = v2 / th;
    float s, c;
    sincosf(th, &s, &c);
    float C = 1.0f - c;
    R[0] = c + C * ux * ux;      R[1] = C * ux * uy - s * uz; R[2] = C * ux * uz + s * uy;
    R[3] = C * uy * ux + s * uz; R[4] = c + C * uy * uy;      R[5] = C * uy * uz - s * ux;
    R[6] = C * uz * ux - s * uy; R[7] = C * uz * uy + s * ux; R[8] = c + C * uz * uz;
}

__device__ __forceinline__ float softplus_f(float x) {
    return fmaxf(x, 0.0f) + log1pf(expf(-fabsf(x)));
}

__global__ __launch_bounds__(THREADS, 2) void so3_kernel(
    const float* __restrict__ x,   const float* __restrict__ eps,
    const float* __restrict__ Wmu, const float* __restrict__ bmu,
    const float* __restrict__ Wd,  const float* __restrict__ bd,
    const float* __restrict__ Wl,  const float* __restrict__ bl,
    float* __restrict__ out, int B, int K, int n)
{
    extern __shared__ float smem[];
    float* Wt = smem;            // [9][K]  transposed, j-major
    float* xs = smem + 9 * K;    // [ROWS][XPAD]

    const int tid = threadIdx.x;

    // Load W transposed: Wt[j][k]; j 0..2 = Wmu cols, 3..5 = Wd, 6..8 = Wl
    for (int idx = tid; idx < 9 * K; idx += THREADS) {
        int j = idx / K;
        int k = idx - j * K;
        float v;
        if (j < 3)      v = Wmu[k * 3 + j];
        else if (j < 6) v = Wd [k * 3 + (j - 3)];
        else            v = Wl [k * 3 + (j - 6)];
        Wt[j * K + k] = v;
    }
    __syncthreads();

    const int row0 = blockIdx.x * ROWS;
    const int Kq = K >> 2;                       // float4 per row
    const float4* __restrict__ x4 = (const float4*)x;

    u64 acc[9];
    #pragma unroll
    for (int j = 0; j < 9; ++j) acc[j] = 0ull;   // {0.f, 0.f}

    for (int kc = 0; kc < K; kc += KC) {
        // ---- stage x tile: ROWS x KC floats, coalesced LDG.128 ----
        #pragma unroll
        for (int i = 0; i < (ROWS * KC / 4) / THREADS; ++i) {   // 16 iters
            int idx = tid + i * THREADS;
            int rrow = idx >> 4;                 // KC/4 = 16 float4 per row
            int q    = idx & 15;
            float4 v = make_float4(0.f, 0.f, 0.f, 0.f);
            int gr = row0 + rrow;
            if (gr < B) v = x4[(long long)gr * Kq + (kc >> 2) + q];
            float* dst = xs + rrow * XPAD + q * 4;
            *(float2*)(dst)     = make_float2(v.x, v.y);
            *(float2*)(dst + 2) = make_float2(v.z, v.w);
        }
        __syncthreads();

        // ---- accumulate 9 dot products over this chunk, packed f32x2 over (k,k+1) ----
        const u64* __restrict__ xr = (const u64*)(xs + tid * XPAD);
        #pragma unroll
        for (int k2 = 0; k2 < KC / 2; ++k2) {
            u64 xv = xr[k2];
            #pragma unroll
            for (int j = 0; j < 9; ++j) {
                u64 wv = *(const u64*)(Wt + j * K + kc + 2 * k2);  // warp-uniform -> broadcast
                asm("fma.rn.f32x2 %0, %1, %2, %0;" : "+l"(acc[j]) : "l"(xv), "l"(wv));
            }
        }
        __syncthreads();
    }

    // ---- epilogue: one row per thread ----
    const int r = row0 + tid;
    if (r >= B) return;

    float s9[9];
    #pragma unroll
    for (int j = 0; j < 9; ++j) {
        float lo, hi;
        asm("mov.b64 {%0, %1}, %2;" : "=f"(lo), "=f"(hi) : "l"(acc[j]));
        s9[j] = lo + hi;
    }

    float mu0 = s9[0] + bmu[0], mu1 = s9[1] + bmu[1], mu2 = s9[2] + bmu[2];
    float sq0 = sqrtf(softplus_f(s9[3] + bd[0]));
    float sq1 = sqrtf(softplus_f(s9[4] + bd[1]));
    float sq2 = sqrtf(softplus_f(s9[5] + bd[2]));
    float lv0 = s9[6] + bl[0], lv1 = s9[7] + bl[1], lv2 = s9[8] + bl[2];

    float Rm[9];
    rodrigues(mu0, mu1, mu2, Rm);

    for (int nn = 0; nn < n; ++nn) {
        const float* e = eps + ((long long)nn * B + r) * 3;
        float t0 = sq0 * e[0];
        float t1 = sq1 * e[1];
        float t2 = sq2 * e[2];
        // v = L @ t with unit lower-triangular L
        float v0 = t0;
        float v1 = fmaf(lv0, t0, t1);
        float v2 = fmaf(lv1, t0, fmaf(lv2, t1, t2));

        float Rv[9];
        rodrigues(v0, v1, v2, Rv);

        float* o = out + ((long long)nn * B + r) * 9;
        #pragma unroll
        for (int i = 0; i < 3; ++i) {
            #pragma unroll
            for (int j = 0; j < 3; ++j) {
                o[i * 3 + j] = Rm[i * 3 + 0] * Rv[0 + j]
                             + Rm[i * 3 + 1] * Rv[3 + j]
                             + Rm[i * 3 + 2] * Rv[6 + j];
            }
        }
    }
}

extern "C" void kernel_launch(void* const* d_in, const int* in_sizes, int n_in,
                              void* d_out, int out_size)
{
    const float* x   = (const float*)d_in[0];
    const float* eps = (const float*)d_in[1];
    const float* Wmu = (const float*)d_in[2];
    const float* bmu = (const float*)d_in[3];
    const float* Wd  = (const float*)d_in[4];
    const float* bd  = (const float*)d_in[5];
    const float* Wl  = (const float*)d_in[6];
    const float* bl  = (const float*)d_in[7];
    float* out = (float*)d_out;

    const int K = in_sizes[2] / 3;            // 1024
    const int B = in_sizes[0] / K;            // 65536
    const int n = in_sizes[1] / (3 * B);      // 1

    size_t smem = (size_t)(9 * K + ROWS * XPAD) * sizeof(float);  // ~104.4 KB
    cudaFuncSetAttribute(so3_kernel, cudaFuncAttributeMaxDynamicSharedMemorySize, (int)smem);

    dim3 grid((B + ROWS - 1) / ROWS);
    so3_kernel<<<grid, THREADS, smem>>>(x, eps, Wmu, bmu, Wd, bd, Wl, bl, out, B, K, n);
}

// round 2
// speedup vs baseline: 1.1622x; 1.1622x over previous
#include <cuda_runtime.h>

#define THREADS 128
#define WARPS (THREADS / 32)
#define ROWS_PER_WARP 8
#define ROWS_PER_BLOCK (WARPS * ROWS_PER_WARP)   // 32
#define KDIM 1024

typedef unsigned long long u64;

__device__ __forceinline__ u64 pack2(float lo, float hi) {
    u64 r;
    asm("mov.b64 %0, {%1, %2};" : "=l"(r) : "f"(lo), "f"(hi));
    return r;
}

__device__ __forceinline__ void unpack2(u64 v, float& lo, float& hi) {
    asm("mov.b64 {%0, %1}, %2;" : "=f"(lo), "=f"(hi) : "l"(v));
}

__device__ __forceinline__ void rodrigues(float v0, float v1, float v2, float* R) {
    float th = sqrtf(v0 * v0 + v1 * v1 + v2 * v2);
    float ux = v0 / th, uy = v1 / th, uz = v2 / th;
    float s, c;
    sincosf(th, &s, &c);
    float C = 1.0f - c;
    R[0] = c + C * ux * ux;      R[1] = C * ux * uy - s * uz; R[2] = C * ux * uz + s * uy;
    R[3] = C * uy * ux + s * uz; R[4] = c + C * uy * uy;      R[5] = C * uy * uz - s * ux;
    R[6] = C * uz * ux - s * uy; R[7] = C * uz * uy + s * ux; R[8] = c + C * uz * uz;
}

__device__ __forceinline__ float softplus_f(float x) {
    return fmaxf(x, 0.0f) + log1pf(expf(-fabsf(x)));
}

__global__ __launch_bounds__(THREADS, 5) void so3_kernel(
    const float* __restrict__ x,   const float* __restrict__ eps,
    const float* __restrict__ Wmu, const float* __restrict__ bmu,
    const float* __restrict__ Wd,  const float* __restrict__ bd,
    const float* __restrict__ Wl,  const float* __restrict__ bl,
    float* __restrict__ out, int B, int n)
{
    __shared__ __align__(16) float Wt[9 * KDIM];   // 36.9 KB, j-major transposed

    const int tid = threadIdx.x;

    // Stage W transposed: Wt[j][k]
    #pragma unroll
    for (int i = 0; i < (9 * KDIM) / THREADS; ++i) {
        int idx = tid + i * THREADS;
        int j = idx >> 10;           // / KDIM
        int k = idx & (KDIM - 1);
        float v;
        if (j < 3)      v = Wmu[k * 3 + j];
        else if (j < 6) v = Wd [k * 3 + (j - 3)];
        else            v = Wl [k * 3 + (j - 6)];
        Wt[j * KDIM + k] = v;
    }
    __syncthreads();

    const int lane = tid & 31;
    const int wid  = tid >> 5;
    const int sub  = lane & 3;       // k-quad id within 16-k group
    const int rloc = lane >> 2;      // row within warp, 0..7
    const int row  = blockIdx.x * ROWS_PER_BLOCK + wid * ROWS_PER_WARP + rloc;

    const longlong2* __restrict__ xp =
        (const longlong2*)(x + (long long)row * KDIM + sub * 4);
    const float* wbase = Wt + sub * 4;

    u64 acc[9];
    #pragma unroll
    for (int j = 0; j < 9; ++j) acc[j] = 0ull;

    // K = 1024 = 64 groups of 16 k's; lane covers k = 16g + 4*sub + {0..3}
    #pragma unroll 4
    for (int g = 0; g < KDIM / 16; ++g) {
        longlong2 xv = xp[g * 4];                 // LDG.128: 64B per row-quad
        u64 x01 = (u64)xv.x, x23 = (u64)xv.y;
        #pragma unroll
        for (int j = 0; j < 9; ++j) {
            longlong2 wv = *(const longlong2*)(wbase + j * KDIM + g * 16);  // LDS.128, 4-addr bcast
            asm("fma.rn.f32x2 %0, %1, %2, %0;" : "+l"(acc[j]) : "l"(x01), "l"((u64)wv.x));
            asm("fma.rn.f32x2 %0, %1, %2, %0;" : "+l"(acc[j]) : "l"(x23), "l"((u64)wv.y));
        }
    }

    // Horizontal add within f32x2, then butterfly-reduce across the 4 sub-lanes
    float s9[9];
    #pragma unroll
    for (int j = 0; j < 9; ++j) {
        float lo, hi;
        unpack2(acc[j], lo, hi);
        s9[j] = lo + hi;
    }
    #pragma unroll
    for (int d = 1; d <= 2; d <<= 1) {
        #pragma unroll
        for (int j = 0; j < 9; ++j)
            s9[j] += __shfl_xor_sync(0xffffffffu, s9[j], d);
    }

    if (sub != 0 || row >= B) return;

    float mu0 = s9[0] + __ldg(bmu + 0), mu1 = s9[1] + __ldg(bmu + 1), mu2 = s9[2] + __ldg(bmu + 2);
    float sq0 = sqrtf(softplus_f(s9[3] + __ldg(bd + 0)));
    float sq1 = sqrtf(softplus_f(s9[4] + __ldg(bd + 1)));
    float sq2 = sqrtf(softplus_f(s9[5] + __ldg(bd + 2)));
    float lv0 = s9[6] + __ldg(bl + 0), lv1 = s9[7] + __ldg(bl + 1), lv2 = s9[8] + __ldg(bl + 2);

    float Rm[9];
    rodrigues(mu0, mu1, mu2, Rm);

    for (int nn = 0; nn < n; ++nn) {
        const float* e = eps + ((long long)nn * B + row) * 3;
        float t0 = sq0 * e[0];
        float t1 = sq1 * e[1];
        float t2 = sq2 * e[2];
        float v0 = t0;
        float v1 = fmaf(lv0, t0, t1);
        float v2 = fmaf(lv1, t0, fmaf(lv2, t1, t2));

        float Rv[9];
        rodrigues(v0, v1, v2, Rv);

        float* o = out + ((long long)nn * B + row) * 9;
        #pragma unroll
        for (int i = 0; i < 3; ++i) {
            #pragma unroll
            for (int j = 0; j < 3; ++j) {
                o[i * 3 + j] = Rm[i * 3 + 0] * Rv[0 + j]
                             + Rm[i * 3 + 1] * Rv[3 + j]
                             + Rm[i * 3 + 2] * Rv[6 + j];
            }
        }
    }
}

extern "C" void kernel_launch(void* const* d_in, const int* in_sizes, int n_in,
                              void* d_out, int out_size)
{
    const float* x   = (const float*)d_in[0];
    const float* eps = (const float*)d_in[1];
    const float* Wmu = (const float*)d_in[2];
    const float* bmu = (const float*)d_in[3];
    const float* Wd  = (const float*)d_in[4];
    const float* bd  = (const float*)d_in[5];
    const float* Wl  = (const float*)d_in[6];
    const float* bl  = (const float*)d_in[7];
    float* out = (float*)d_out;

    const int B = in_sizes[0] / KDIM;         // 65536
    const int n = in_sizes[1] / (3 * B);      // 1

    dim3 grid((B + ROWS_PER_BLOCK - 1) / ROWS_PER_BLOCK);   // 2048
    so3_kernel<<<grid, THREADS>>>(x, eps, Wmu, bmu, Wd, bd, Wl, bl, out, B, n);
}